// round 3
// baseline (speedup 1.0000x reference)
#include <cuda_runtime.h>
#include <math.h>

#define BATCH 256
#define TT    1024
#define HID   512
#define G4    2048   /* 4*HID */
#define NB    384    /* persistent grid size (must all be resident: 3/SM * 148 = 444 >= 384) */
#define NT    256

// ---------------- static device state ----------------
__device__ float g_h1[2][BATCH * HID];   // layer1 h ping-pong
__device__ float g_h2[2][BATCH * HID];   // layer2 h ping-pong
__device__ float g_c1[BATCH * HID];
__device__ float g_c2[BATCH * HID];
__device__ float g_zero[BATCH * HID];
__device__ float g_p1[2][BATCH * G4];    // layer1 K-split partials
__device__ float g_p2[4][BATCH * G4];    // layer2 partials
__device__ unsigned g_cnt;               // monotonic barrier counter

__global__ void init_kernel() {
    int i = blockIdx.x * blockDim.x + threadIdx.x;
    if (i == 0) g_cnt = 0u;
    if (i < BATCH * HID) {
        g_c1[i] = 0.f;
        g_c2[i] = 0.f;
        g_zero[i] = 0.f;
    }
}

__device__ __forceinline__ float sigf(float v) { return 1.f / (1.f + expf(-v)); }

// Grid barrier: monotonic counter, no reset -> no reset/reuse race.
// Caller passes target = (barrier ordinal) * NB.
__device__ __forceinline__ void gbar(unsigned target) {
    __syncthreads();
    if (threadIdx.x == 0) {
        __threadfence();                 // publish this block's writes
        atomicAdd(&g_cnt, 1u);
        volatile unsigned* p = &g_cnt;
        while (*p < target) { __nanosleep(32); }
    }
    __syncthreads();
}

// ---------------- persistent fused kernel ----------------
// Per iteration k (0..TT):
//   phase A (GEMM): blocks 0..127   -> layer1 step k   (2 K-splits of Whh1)
//                   blocks 128..383 -> layer2 step k-1 (4 splits: Wih2 x2, Whh2 x2)
//   barrier
//   phase B (cell): all blocks update gates/c/h for both layers
//   barrier
__global__ __launch_bounds__(NT, 3)
void lstm_persist(const float* __restrict__ x,
                  const float* __restrict__ Wih1,
                  const float* __restrict__ Whh1,
                  const float* __restrict__ bih1,
                  const float* __restrict__ bhh1,
                  const float* __restrict__ Wih2,
                  const float* __restrict__ Whh2,
                  const float* __restrict__ bih2,
                  const float* __restrict__ bhh2,
                  float* __restrict__ out) {
    __shared__ float As[64 * 33];    // A[b][kk], padded -> conflict-free
    __shared__ float Ws[128 * 33];   // W[c][kk]

    const int bid = blockIdx.x;
    const int t   = threadIdx.x;
    const int hh  = t & 15;          // hidden sub-index (cols hh, hh+16)
    const int bi  = t >> 4;          // batch group (rows bi*4 .. bi*4+3)

    // per-block constant tile parameters
    int b0, h0, kbeg, which;         // which: 0=L1, 1=L2-ih, 2=L2-hh
    const float* W;
    float* outp;
    if (bid < 128) {
        int tile = bid >> 1, sp = bid & 1;
        b0 = (tile & 3) * 64;
        h0 = (tile >> 2) * 32;
        kbeg = sp * 256;
        W = Whh1; outp = g_p1[sp]; which = 0;
    } else {
        int id = bid - 128;
        int tile = id >> 2, sp = id & 3;
        b0 = (tile & 3) * 64;
        h0 = (tile >> 2) * 32;
        kbeg = (sp & 1) * 256;
        if (sp < 2) { W = Wih2; which = 1; }
        else        { W = Whh2; which = 2; }
        outp = g_p2[sp];
    }

    unsigned bt = 0;

    for (int k = 0; k <= TT; k++) {
        // ---------- phase A: GEMM partials ----------
        bool active = (which == 0) ? (k < TT) : (k >= 1);
        if (active) {
            const float* A;
            if (which == 0) {
                A = (k == 0) ? g_zero : g_h1[(k - 1) & 1];
            } else {
                int s = k - 1;
                A = (which == 1) ? g_h1[s & 1]
                                 : ((s == 0) ? g_zero : g_h2[(s - 1) & 1]);
            }

            float acc[4][8];
#pragma unroll
            for (int j = 0; j < 4; j++)
#pragma unroll
                for (int c = 0; c < 8; c++) acc[j][c] = 0.f;

            for (int kc = 0; kc < 256; kc += 32) {
#pragma unroll
                for (int i = 0; i < 8; i++) {
                    int e = t + 256 * i;
                    int kk = e & 31, b = e >> 5;
                    // __ldcg: h buffers are written by other SMs within this launch
                    As[b * 33 + kk] = __ldcg(&A[(b0 + b) * HID + kbeg + kc + kk]);
                }
#pragma unroll
                for (int i = 0; i < 16; i++) {
                    int e = t + 256 * i;
                    int kk = e & 31, c = e >> 5;
                    int row = (c >> 5) * HID + h0 + (c & 31);
                    Ws[c * 33 + kk] = __ldg(&W[row * HID + kbeg + kc + kk]);
                }
                __syncthreads();

#pragma unroll
                for (int kk = 0; kk < 32; kk++) {
                    float a[4], w[8];
#pragma unroll
                    for (int j = 0; j < 4; j++) a[j] = As[(bi * 4 + j) * 33 + kk];
#pragma unroll
                    for (int g = 0; g < 4; g++) {
                        w[g * 2 + 0] = Ws[(g * 32 + hh) * 33 + kk];
                        w[g * 2 + 1] = Ws[(g * 32 + hh + 16) * 33 + kk];
                    }
#pragma unroll
                    for (int j = 0; j < 4; j++)
#pragma unroll
                        for (int c = 0; c < 8; c++) acc[j][c] += a[j] * w[c];
                }
                __syncthreads();
            }

#pragma unroll
            for (int j = 0; j < 4; j++) {
                int b = b0 + bi * 4 + j;
#pragma unroll
                for (int c = 0; c < 8; c++) {
                    int g = c >> 1;
                    int hid = h0 + hh + (c & 1) * 16;
                    outp[b * G4 + g * HID + hid] = acc[j][c];
                }
            }
        }

        bt += NB; gbar(bt);

        // ---------- phase B: cell update ----------
        for (int e = bid * NT + t; e < 2 * BATCH * HID; e += NB * NT) {
            int layer = e >> 17;
            int r = e & (BATCH * HID - 1);
            int b = r >> 9;
            int h = r & (HID - 1);

            if (layer == 0) {
                if (k < TT) {
                    float xv = x[b * TT + k];
                    float pre[4];
#pragma unroll
                    for (int g = 0; g < 4; g++) {
                        int row = g * HID + h;
                        pre[g] = __ldcg(&g_p1[0][b * G4 + row])
                               + __ldcg(&g_p1[1][b * G4 + row])
                               + bih1[row] + bhh1[row] + xv * Wih1[row];
                    }
                    float i_ = sigf(pre[0]);
                    float f_ = sigf(pre[1]);
                    float gg = tanhf(pre[2]);
                    float o_ = sigf(pre[3]);
                    float c = f_ * g_c1[r] + i_ * gg;   // c owned by this thread
                    g_c1[r] = c;
                    g_h1[k & 1][r] = o_ * tanhf(c);
                }
            } else {
                if (k >= 1) {
                    int s = k - 1;
                    float pre[4];
#pragma unroll
                    for (int g = 0; g < 4; g++) {
                        int row = g * HID + h;
                        float v = bih2[row] + bhh2[row];
#pragma unroll
                        for (int sp = 0; sp < 4; sp++)
                            v += __ldcg(&g_p2[sp][b * G4 + row]);
                        pre[g] = v;
                    }
                    float i_ = sigf(pre[0]);
                    float f_ = sigf(pre[1]);
                    float gg = tanhf(pre[2]);
                    float o_ = sigf(pre[3]);
                    float c = f_ * g_c2[r] + i_ * gg;
                    g_c2[r] = c;
                    float hv = o_ * tanhf(c);
                    g_h2[s & 1][r] = hv;
                    if (s == TT - 1) out[r] = hv;
                }
            }
        }

        bt += NB; gbar(bt);
    }
}

// ---------------- launch: 2 graph nodes total ----------------
extern "C" void kernel_launch(void* const* d_in, const int* in_sizes, int n_in,
                              void* d_out, int out_size) {
    (void)in_sizes; (void)n_in; (void)out_size;
    const float* x    = (const float*)d_in[0];
    const float* Wih1 = (const float*)d_in[1];
    const float* Whh1 = (const float*)d_in[2];
    const float* bih1 = (const float*)d_in[3];
    const float* bhh1 = (const float*)d_in[4];
    const float* Wih2 = (const float*)d_in[5];
    const float* Whh2 = (const float*)d_in[6];
    const float* bih2 = (const float*)d_in[7];
    const float* bhh2 = (const float*)d_in[8];
    float* out = (float*)d_out;

    init_kernel<<<512, 256>>>();
    lstm_persist<<<NB, NT>>>(x, Wih1, Whh1, bih1, bhh1,
                             Wih2, Whh2, bih2, bhh2, out);
}

// round 4
// speedup vs baseline: 1.0014x; 1.0014x over previous
#include <cuda_runtime.h>
#include <math.h>

#define BATCH 256
#define TT    1024
#define HID   512
#define G4    2048   /* 4*HID */
#define NB    384    /* persistent grid size (must all be resident: 3/SM * 148 = 444 >= 384) */
#define NT    256

// ---------------- static device state ----------------
__device__ float g_h1[2][BATCH * HID];   // layer1 h ping-pong
__device__ float g_h2[2][BATCH * HID];   // layer2 h ping-pong
__device__ float g_c1[BATCH * HID];
__device__ float g_c2[BATCH * HID];
__device__ float g_zero[BATCH * HID];
__device__ float g_p1[2][BATCH * G4];    // layer1 K-split partials
__device__ float g_p2[4][BATCH * G4];    // layer2 partials
__device__ unsigned g_cnt;               // monotonic barrier counter

__global__ void init_kernel() {
    int i = blockIdx.x * blockDim.x + threadIdx.x;
    if (i == 0) g_cnt = 0u;
    if (i < BATCH * HID) {
        g_c1[i] = 0.f;
        g_c2[i] = 0.f;
        g_zero[i] = 0.f;
    }
}

__device__ __forceinline__ float sigf(float v) { return 1.f / (1.f + expf(-v)); }

// Grid barrier: monotonic counter, no reset -> no reset/reuse race.
// Caller passes target = (barrier ordinal) * NB.
__device__ __forceinline__ void gbar(unsigned target) {
    __syncthreads();
    if (threadIdx.x == 0) {
        __threadfence();                 // publish this block's writes
        atomicAdd(&g_cnt, 1u);
        volatile unsigned* p = &g_cnt;
        while (*p < target) { __nanosleep(32); }
    }
    __syncthreads();
}

// ---------------- persistent fused kernel ----------------
// Per iteration k (0..TT):
//   phase A (GEMM): blocks 0..127   -> layer1 step k   (2 K-splits of Whh1)
//                   blocks 128..383 -> layer2 step k-1 (4 splits: Wih2 x2, Whh2 x2)
//   barrier
//   phase B (cell): all blocks update gates/c/h for both layers
//   barrier
__global__ __launch_bounds__(NT, 3)
void lstm_persist(const float* __restrict__ x,
                  const float* __restrict__ Wih1,
                  const float* __restrict__ Whh1,
                  const float* __restrict__ bih1,
                  const float* __restrict__ bhh1,
                  const float* __restrict__ Wih2,
                  const float* __restrict__ Whh2,
                  const float* __restrict__ bih2,
                  const float* __restrict__ bhh2,
                  float* __restrict__ out) {
    __shared__ float As[64 * 33];    // A[b][kk], padded -> conflict-free
    __shared__ float Ws[128 * 33];   // W[c][kk]

    const int bid = blockIdx.x;
    const int t   = threadIdx.x;
    const int hh  = t & 15;          // hidden sub-index (cols hh, hh+16)
    const int bi  = t >> 4;          // batch group (rows bi*4 .. bi*4+3)

    // per-block constant tile parameters
    int b0, h0, kbeg, which;         // which: 0=L1, 1=L2-ih, 2=L2-hh
    const float* W;
    float* outp;
    if (bid < 128) {
        int tile = bid >> 1, sp = bid & 1;
        b0 = (tile & 3) * 64;
        h0 = (tile >> 2) * 32;
        kbeg = sp * 256;
        W = Whh1; outp = g_p1[sp]; which = 0;
    } else {
        int id = bid - 128;
        int tile = id >> 2, sp = id & 3;
        b0 = (tile & 3) * 64;
        h0 = (tile >> 2) * 32;
        kbeg = (sp & 1) * 256;
        if (sp < 2) { W = Wih2; which = 1; }
        else        { W = Whh2; which = 2; }
        outp = g_p2[sp];
    }

    unsigned bt = 0;

    for (int k = 0; k <= TT; k++) {
        // ---------- phase A: GEMM partials ----------
        bool active = (which == 0) ? (k < TT) : (k >= 1);
        if (active) {
            const float* A;
            if (which == 0) {
                A = (k == 0) ? g_zero : g_h1[(k - 1) & 1];
            } else {
                int s = k - 1;
                A = (which == 1) ? g_h1[s & 1]
                                 : ((s == 0) ? g_zero : g_h2[(s - 1) & 1]);
            }

            float acc[4][8];
#pragma unroll
            for (int j = 0; j < 4; j++)
#pragma unroll
                for (int c = 0; c < 8; c++) acc[j][c] = 0.f;

            for (int kc = 0; kc < 256; kc += 32) {
#pragma unroll
                for (int i = 0; i < 8; i++) {
                    int e = t + 256 * i;
                    int kk = e & 31, b = e >> 5;
                    // __ldcg: h buffers are written by other SMs within this launch
                    As[b * 33 + kk] = __ldcg(&A[(b0 + b) * HID + kbeg + kc + kk]);
                }
#pragma unroll
                for (int i = 0; i < 16; i++) {
                    int e = t + 256 * i;
                    int kk = e & 31, c = e >> 5;
                    int row = (c >> 5) * HID + h0 + (c & 31);
                    Ws[c * 33 + kk] = __ldg(&W[row * HID + kbeg + kc + kk]);
                }
                __syncthreads();

#pragma unroll
                for (int kk = 0; kk < 32; kk++) {
                    float a[4], w[8];
#pragma unroll
                    for (int j = 0; j < 4; j++) a[j] = As[(bi * 4 + j) * 33 + kk];
#pragma unroll
                    for (int g = 0; g < 4; g++) {
                        w[g * 2 + 0] = Ws[(g * 32 + hh) * 33 + kk];
                        w[g * 2 + 1] = Ws[(g * 32 + hh + 16) * 33 + kk];
                    }
#pragma unroll
                    for (int j = 0; j < 4; j++)
#pragma unroll
                        for (int c = 0; c < 8; c++) acc[j][c] += a[j] * w[c];
                }
                __syncthreads();
            }

#pragma unroll
            for (int j = 0; j < 4; j++) {
                int b = b0 + bi * 4 + j;
#pragma unroll
                for (int c = 0; c < 8; c++) {
                    int g = c >> 1;
                    int hid = h0 + hh + (c & 1) * 16;
                    outp[b * G4 + g * HID + hid] = acc[j][c];
                }
            }
        }

        bt += NB; gbar(bt);

        // ---------- phase B: cell update ----------
        for (int e = bid * NT + t; e < 2 * BATCH * HID; e += NB * NT) {
            int layer = e >> 17;
            int r = e & (BATCH * HID - 1);
            int b = r >> 9;
            int h = r & (HID - 1);

            if (layer == 0) {
                if (k < TT) {
                    float xv = x[b * TT + k];
                    float pre[4];
#pragma unroll
                    for (int g = 0; g < 4; g++) {
                        int row = g * HID + h;
                        pre[g] = __ldcg(&g_p1[0][b * G4 + row])
                               + __ldcg(&g_p1[1][b * G4 + row])
                               + bih1[row] + bhh1[row] + xv * Wih1[row];
                    }
                    float i_ = sigf(pre[0]);
                    float f_ = sigf(pre[1]);
                    float gg = tanhf(pre[2]);
                    float o_ = sigf(pre[3]);
                    float c = f_ * g_c1[r] + i_ * gg;   // c owned by this thread
                    g_c1[r] = c;
                    g_h1[k & 1][r] = o_ * tanhf(c);
                }
            } else {
                if (k >= 1) {
                    int s = k - 1;
                    float pre[4];
#pragma unroll
                    for (int g = 0; g < 4; g++) {
                        int row = g * HID + h;
                        float v = bih2[row] + bhh2[row];
#pragma unroll
                        for (int sp = 0; sp < 4; sp++)
                            v += __ldcg(&g_p2[sp][b * G4 + row]);
                        pre[g] = v;
                    }
                    float i_ = sigf(pre[0]);
                    float f_ = sigf(pre[1]);
                    float gg = tanhf(pre[2]);
                    float o_ = sigf(pre[3]);
                    float c = f_ * g_c2[r] + i_ * gg;
                    g_c2[r] = c;
                    float hv = o_ * tanhf(c);
                    g_h2[s & 1][r] = hv;
                    if (s == TT - 1) out[r] = hv;
                }
            }
        }

        bt += NB; gbar(bt);
    }
}

// ---------------- launch: 2 graph nodes total ----------------
extern "C" void kernel_launch(void* const* d_in, const int* in_sizes, int n_in,
                              void* d_out, int out_size) {
    (void)in_sizes; (void)n_in; (void)out_size;
    const float* x    = (const float*)d_in[0];
    const float* Wih1 = (const float*)d_in[1];
    const float* Whh1 = (const float*)d_in[2];
    const float* bih1 = (const float*)d_in[3];
    const float* bhh1 = (const float*)d_in[4];
    const float* Wih2 = (const float*)d_in[5];
    const float* Whh2 = (const float*)d_in[6];
    const float* bih2 = (const float*)d_in[7];
    const float* bhh2 = (const float*)d_in[8];
    float* out = (float*)d_out;

    init_kernel<<<512, 256>>>();
    lstm_persist<<<NB, NT>>>(x, Wih1, Whh1, bih1, bhh1,
                             Wih2, Whh2, bih2, bhh2, out);
}

// round 5
// speedup vs baseline: 2.1807x; 2.1776x over previous
#include <cuda_runtime.h>
#include <math.h>
#include <stdint.h>

#define BATCH 256
#define TT    1024
#define HID   512
#define G4    2048
#define NB    296
#define NT    256
#define NTILES 768

__device__ float g_h1t[2][BATCH * HID];
__device__ float g_h2t[2][BATCH * HID];
__device__ float g_p1[2][BATCH * G4];
__device__ float g_p2[4][BATCH * G4];
__device__ float g_wWhh1[G4 * HID];
__device__ float g_wWih2[G4 * HID];
__device__ float g_wWhh2[G4 * HID];
__device__ float g_bs1[G4];
__device__ float g_bs2[G4];
__device__ unsigned g_cnt;

__device__ __forceinline__ float tf32r(float x) {
    uint32_t u;
    asm("cvt.rna.tf32.f32 %0, %1;" : "=r"(u) : "f"(x));
    return __uint_as_float(u);
}

__global__ void init_kernel(const float* __restrict__ Whh1,
                            const float* __restrict__ Wih2,
                            const float* __restrict__ Whh2,
                            const float* __restrict__ bih1, const float* __restrict__ bhh1,
                            const float* __restrict__ bih2, const float* __restrict__ bhh2) {
    int i = blockIdx.x * blockDim.x + threadIdx.x;
    if (i == 0) g_cnt = 0u;
    if (i < G4 / 4) {
        float4 a = ((const float4*)bih1)[i], b = ((const float4*)bhh1)[i];
        ((float4*)g_bs1)[i] = make_float4(a.x + b.x, a.y + b.y, a.z + b.z, a.w + b.w);
        float4 c = ((const float4*)bih2)[i], d = ((const float4*)bhh2)[i];
        ((float4*)g_bs2)[i] = make_float4(c.x + d.x, c.y + d.y, c.z + d.z, c.w + d.w);
    }
    if (i < G4 * HID / 4) {
        float4 v;
        v = ((const float4*)Whh1)[i];
        ((float4*)g_wWhh1)[i] = make_float4(tf32r(v.x), tf32r(v.y), tf32r(v.z), tf32r(v.w));
        v = ((const float4*)Wih2)[i];
        ((float4*)g_wWih2)[i] = make_float4(tf32r(v.x), tf32r(v.y), tf32r(v.z), tf32r(v.w));
        v = ((const float4*)Whh2)[i];
        ((float4*)g_wWhh2)[i] = make_float4(tf32r(v.x), tf32r(v.y), tf32r(v.z), tf32r(v.w));
    }
}

// ---- MUFU-free activations ----
__device__ __forceinline__ float fexp2_(float y) {
    y = fminf(fmaxf(y, -30.f), 30.f);
    float r = y + 12582912.f;
    int   n = __float_as_int(r) - 0x4B400000;
    float f = y - (r - 12582912.f);
    float p = 1.5403530393381609e-4f;
    p = fmaf(p, f, 1.3333558146428443e-3f);
    p = fmaf(p, f, 9.6181291076284772e-3f);
    p = fmaf(p, f, 5.5504108664821580e-2f);
    p = fmaf(p, f, 2.4022650695910071e-1f);
    p = fmaf(p, f, 6.9314718055994531e-1f);
    p = fmaf(p, f, 1.0f);
    return p * __int_as_float((n + 127) << 23);
}
__device__ __forceinline__ float frcp_(float d) {
    float w = __int_as_float(0x7EF311C3 - __float_as_int(d));
    w = w * (2.f - d * w);
    w = w * (2.f - d * w);
    w = w * (2.f - d * w);
    return w;
}
__device__ __forceinline__ float sigf(float v) {
    float E = fexp2_(v * 1.4426950408889634f);
    return E * frcp_(1.f + E);
}
__device__ __forceinline__ float tanhf_(float v) {
    float E = fexp2_(v * 2.8853900817779268f);
    return (E - 1.f) * frcp_(E + 1.f);
}
__device__ __forceinline__ float4 sig4(float4 v) {
    return make_float4(sigf(v.x), sigf(v.y), sigf(v.z), sigf(v.w));
}
__device__ __forceinline__ float4 tanh4(float4 v) {
    return make_float4(tanhf_(v.x), tanhf_(v.y), tanhf_(v.z), tanhf_(v.w));
}

__device__ __forceinline__ void gbar(unsigned target) {
    __syncthreads();
    if (threadIdx.x == 0) {
        __threadfence();
        atomicAdd(&g_cnt, 1u);
        volatile unsigned* p = &g_cnt;
        while (*p < target) { __nanosleep(32); }
    }
    __syncthreads();
}

__global__ __launch_bounds__(NT, 2)
void lstm_persist(const float* __restrict__ x,
                  const float* __restrict__ Wih1,
                  float* __restrict__ out) {
    __shared__ __align__(16) float As[2][64 * 36];
    __shared__ __align__(16) float Bs[2][64 * 36];

    const int t = threadIdx.x, bid = blockIdx.x;
    const int w = t >> 5, lane = t & 31;
    const int g4l = lane >> 2, ql = lane & 3;
    const int wm = w & 3, wn = w >> 2;
    const int arow0 = t >> 3, ac4 = t & 7;

    // one float4 cell item per thread
    const int it = bid * NT + t;
    const bool own = it < 2 * BATCH * HID / 4;
    int layer = 0, cb = 0, ch4 = 0;
    if (own) { layer = it >> 15; int r4 = it & 32767; cb = r4 >> 7; ch4 = r4 & 127; }
    float4 cc = make_float4(0.f, 0.f, 0.f, 0.f);

    unsigned bt = 0;

    for (int k = 0; k <= TT; k++) {
        // ============ phase A: GEMM tiles (static assignment) ============
        for (int tt = bid; tt < NTILES; tt += NB) {
            int gm = tt >> 8, r = tt & 255;
            int sp = r & 1, q2 = r >> 1;
            int b0 = (q2 & 3) << 6, n0 = (q2 >> 2) << 6, kbeg = sp << 8;

            bool active, zeroA = false;
            const float* Ap; const float* Wp; float* outp;
            if (gm == 0) {            // L1: h1[k-1] @ Whh1^T
                active = (k < TT); zeroA = (k == 0);
                Ap = g_h1t[(k - 1) & 1]; Wp = g_wWhh1; outp = g_p1[sp];
            } else if (gm == 1) {     // L2-ih: h1[k-1] @ Wih2^T
                active = (k >= 1); 
                Ap = g_h1t[(k - 1) & 1]; Wp = g_wWih2; outp = g_p2[sp];
            } else {                  // L2-hh: h2[k-2] @ Whh2^T
                active = (k >= 1); zeroA = (k == 1);
                Ap = g_h2t[k & 1];    Wp = g_wWhh2; outp = g_p2[2 + sp];
            }
            if (!active) continue;

            if (zeroA) {
                float4 z = make_float4(0.f, 0.f, 0.f, 0.f);
#pragma unroll
                for (int i = 0; i < 4; i++) {
                    int e = t + 256 * i;
                    int rr = e >> 4, c4 = e & 15;
                    ((float4*)outp)[(b0 + rr) * (G4 / 4) + (n0 >> 2) + c4] = z;
                }
                continue;
            }

            const float4* Ap4 = (const float4*)Ap;
            const float4* Wp4 = (const float4*)Wp;
            const int kb4 = kbeg >> 2;

            float4 sa0 = __ldcg(&Ap4[(b0 + arow0) * 128 + kb4 + ac4]);
            float4 sa1 = __ldcg(&Ap4[(b0 + arow0 + 32) * 128 + kb4 + ac4]);
            float4 sb0 = Wp4[(n0 + arow0) * 128 + kb4 + ac4];
            float4 sb1 = Wp4[(n0 + arow0 + 32) * 128 + kb4 + ac4];

            float acc[4][4];
#pragma unroll
            for (int a = 0; a < 4; a++)
#pragma unroll
                for (int b = 0; b < 4; b++) acc[a][b] = 0.f;

            for (int chn = 0; chn < 8; chn++) {
                int buf = chn & 1;
                *(float4*)&As[buf][arow0 * 36 + ac4 * 4] = sa0;
                *(float4*)&As[buf][(arow0 + 32) * 36 + ac4 * 4] = sa1;
                *(float4*)&Bs[buf][arow0 * 36 + ac4 * 4] = sb0;
                *(float4*)&Bs[buf][(arow0 + 32) * 36 + ac4 * 4] = sb1;
                __syncthreads();
                if (chn < 7) {
                    int o = kb4 + (chn + 1) * 8 + ac4;
                    sa0 = __ldcg(&Ap4[(b0 + arow0) * 128 + o]);
                    sa1 = __ldcg(&Ap4[(b0 + arow0 + 32) * 128 + o]);
                    sb0 = Wp4[(n0 + arow0) * 128 + o];
                    sb1 = Wp4[(n0 + arow0 + 32) * 128 + o];
                }
                const uint32_t* AsU = (const uint32_t*)As[buf];
                const uint32_t* BsU = (const uint32_t*)Bs[buf];
#pragma unroll
                for (int s8 = 0; s8 < 4; s8++) {
                    int abase = (wm * 16 + g4l) * 36 + s8 * 8 + ql;
                    uint32_t a0 = AsU[abase];
                    uint32_t a1 = AsU[abase + 8 * 36];
                    uint32_t a2 = AsU[abase + 4];
                    uint32_t a3 = AsU[abase + 8 * 36 + 4];
#pragma unroll
                    for (int t8 = 0; t8 < 4; t8++) {
                        int bbase = (wn * 32 + t8 * 8 + g4l) * 36 + s8 * 8 + ql;
                        uint32_t br0 = BsU[bbase], br1 = BsU[bbase + 4];
                        asm volatile(
                            "mma.sync.aligned.m16n8k8.row.col.f32.tf32.tf32.f32 "
                            "{%0,%1,%2,%3},{%4,%5,%6,%7},{%8,%9},{%0,%1,%2,%3};"
                            : "+f"(acc[t8][0]), "+f"(acc[t8][1]),
                              "+f"(acc[t8][2]), "+f"(acc[t8][3])
                            : "r"(a0), "r"(a1), "r"(a2), "r"(a3), "r"(br0), "r"(br1));
                    }
                }
                __syncthreads();
            }

#pragma unroll
            for (int t8 = 0; t8 < 4; t8++) {
                int gc = n0 + wn * 32 + t8 * 8 + 2 * ql;
                int m0 = b0 + wm * 16 + g4l;
                *(float2*)&outp[m0 * G4 + gc] = make_float2(acc[t8][0], acc[t8][1]);
                *(float2*)&outp[(m0 + 8) * G4 + gc] = make_float2(acc[t8][2], acc[t8][3]);
            }
        }

        bt += NB; gbar(bt);

        // ============ phase B: cell update ============
        if (own) {
            if (layer == 0) {
                if (k < TT) {
                    float xv = x[cb * TT + k];
                    float4 pre[4];
#pragma unroll
                    for (int g = 0; g < 4; g++) {
                        int idx = cb * 512 + g * 128 + ch4;
                        float4 pa = __ldcg(&((const float4*)g_p1[0])[idx]);
                        float4 pb = __ldcg(&((const float4*)g_p1[1])[idx]);
                        float4 bs = ((const float4*)g_bs1)[g * 128 + ch4];
                        float4 wv = ((const float4*)Wih1)[g * 128 + ch4];
                        pre[g] = make_float4(pa.x + pb.x + bs.x + xv * wv.x,
                                             pa.y + pb.y + bs.y + xv * wv.y,
                                             pa.z + pb.z + bs.z + xv * wv.z,
                                             pa.w + pb.w + bs.w + xv * wv.w);
                    }
                    float4 iv = sig4(pre[0]), fv = sig4(pre[1]);
                    float4 gv = tanh4(pre[2]), ov = sig4(pre[3]);
                    cc.x = fv.x * cc.x + iv.x * gv.x;
                    cc.y = fv.y * cc.y + iv.y * gv.y;
                    cc.z = fv.z * cc.z + iv.z * gv.z;
                    cc.w = fv.w * cc.w + iv.w * gv.w;
                    float4 tc = tanh4(cc);
                    ((float4*)g_h1t[k & 1])[cb * 128 + ch4] =
                        make_float4(tf32r(ov.x * tc.x), tf32r(ov.y * tc.y),
                                    tf32r(ov.z * tc.z), tf32r(ov.w * tc.w));
                }
            } else {
                if (k >= 1) {
                    int s = k - 1;
                    float4 pre[4];
#pragma unroll
                    for (int g = 0; g < 4; g++) {
                        int idx = cb * 512 + g * 128 + ch4;
                        float4 v = ((const float4*)g_bs2)[g * 128 + ch4];
#pragma unroll
                        for (int spp = 0; spp < 4; spp++) {
                            float4 p = __ldcg(&((const float4*)g_p2[spp])[idx]);
                            v.x += p.x; v.y += p.y; v.z += p.z; v.w += p.w;
                        }
                        pre[g] = v;
                    }
                    float4 iv = sig4(pre[0]), fv = sig4(pre[1]);
                    float4 gv = tanh4(pre[2]), ov = sig4(pre[3]);
                    cc.x = fv.x * cc.x + iv.x * gv.x;
                    cc.y = fv.y * cc.y + iv.y * gv.y;
                    cc.z = fv.z * cc.z + iv.z * gv.z;
                    cc.w = fv.w * cc.w + iv.w * gv.w;
                    float4 tc = tanh4(cc);
                    float4 hv = make_float4(ov.x * tc.x, ov.y * tc.y,
                                            ov.z * tc.z, ov.w * tc.w);
                    ((float4*)g_h2t[s & 1])[cb * 128 + ch4] =
                        make_float4(tf32r(hv.x), tf32r(hv.y), tf32r(hv.z), tf32r(hv.w));
                    if (s == TT - 1) ((float4*)out)[cb * 128 + ch4] = hv;
                }
            }
        }

        bt += NB; gbar(bt);
    }
}

extern "C" void kernel_launch(void* const* d_in, const int* in_sizes, int n_in,
                              void* d_out, int out_size) {
    (void)in_sizes; (void)n_in; (void)out_size;
    const float* x    = (const float*)d_in[0];
    const float* Wih1 = (const float*)d_in[1];
    const float* Whh1 = (const float*)d_in[2];
    const float* bih1 = (const float*)d_in[3];
    const float* bhh1 = (const float*)d_in[4];
    const float* Wih2 = (const float*)d_in[5];
    const float* Whh2 = (const float*)d_in[6];
    const float* bih2 = (const float*)d_in[7];
    const float* bhh2 = (const float*)d_in[8];
    float* out = (float*)d_out;

    init_kernel<<<1024, 256>>>(Whh1, Wih2, Whh2, bih1, bhh1, bih2, bhh2);
    lstm_persist<<<NB, NT>>>(x, Wih1, out);
}

// round 6
// speedup vs baseline: 3.0172x; 1.3836x over previous
#include <cuda_runtime.h>
#include <cuda_fp16.h>
#include <math.h>
#include <stdint.h>

#define BATCH 256
#define TT    1024
#define HID   512
#define G4    2048
#define NT    256
#define NTILES 768
#define SH    40     /* smem row stride in halves (conflict-free: 20*g4l+ql spans 32 banks) */

// ---------------- static device state ----------------
__device__ __half g_h1h[2][BATCH * HID];
__device__ __half g_h2h[2][BATCH * HID];
__device__ __half g_wWhh1h[G4 * HID];
__device__ __half g_wWih2h[G4 * HID];
__device__ __half g_wWhh2h[G4 * HID];
__device__ float  g_p1[2][BATCH * G4];
__device__ float  g_p2[4][BATCH * G4];
__device__ float  g_bs1[G4];
__device__ float  g_bs2[G4];
__device__ float  g_xt[TT * BATCH];      // x transposed: [k][b]
__device__ unsigned g_cnt;

__global__ void init_kernel(const float* __restrict__ x,
                            const float* __restrict__ Whh1,
                            const float* __restrict__ Wih2,
                            const float* __restrict__ Whh2,
                            const float* __restrict__ bih1, const float* __restrict__ bhh1,
                            const float* __restrict__ bih2, const float* __restrict__ bhh2) {
    int i = blockIdx.x * blockDim.x + threadIdx.x;     // 0 .. 262143
    if (i == 0) g_cnt = 0u;
    if (i < G4 / 4) {
        float4 a = ((const float4*)bih1)[i], b = ((const float4*)bhh1)[i];
        ((float4*)g_bs1)[i] = make_float4(a.x + b.x, a.y + b.y, a.z + b.z, a.w + b.w);
        float4 c = ((const float4*)bih2)[i], d = ((const float4*)bhh2)[i];
        ((float4*)g_bs2)[i] = make_float4(c.x + d.x, c.y + d.y, c.z + d.z, c.w + d.w);
    }
    if (i < G4 * HID / 4) {
        float4 v;
        v = ((const float4*)Whh1)[i];
        ((__half2*)g_wWhh1h)[2*i]   = __floats2half2_rn(v.x, v.y);
        ((__half2*)g_wWhh1h)[2*i+1] = __floats2half2_rn(v.z, v.w);
        v = ((const float4*)Wih2)[i];
        ((__half2*)g_wWih2h)[2*i]   = __floats2half2_rn(v.x, v.y);
        ((__half2*)g_wWih2h)[2*i+1] = __floats2half2_rn(v.z, v.w);
        v = ((const float4*)Whh2)[i];
        ((__half2*)g_wWhh2h)[2*i]   = __floats2half2_rn(v.x, v.y);
        ((__half2*)g_wWhh2h)[2*i+1] = __floats2half2_rn(v.z, v.w);
    }
    if (i < BATCH * TT) {               // transpose x
        int b = i >> 10, k = i & 1023;
        g_xt[k * BATCH + b] = x[i];
    }
}

// ---- MUFU-free activations ----
__device__ __forceinline__ float fexp2_(float y) {
    y = fminf(fmaxf(y, -30.f), 30.f);
    float r = y + 12582912.f;
    int   n = __float_as_int(r) - 0x4B400000;
    float f = y - (r - 12582912.f);
    float p = 1.5403530393381609e-4f;
    p = fmaf(p, f, 1.3333558146428443e-3f);
    p = fmaf(p, f, 9.6181291076284772e-3f);
    p = fmaf(p, f, 5.5504108664821580e-2f);
    p = fmaf(p, f, 2.4022650695910071e-1f);
    p = fmaf(p, f, 6.9314718055994531e-1f);
    p = fmaf(p, f, 1.0f);
    return p * __int_as_float((n + 127) << 23);
}
__device__ __forceinline__ float frcp_(float d) {
    float w = __int_as_float(0x7EF311C3 - __float_as_int(d));
    w = w * (2.f - d * w);
    w = w * (2.f - d * w);
    w = w * (2.f - d * w);
    return w;
}
__device__ __forceinline__ float sigf(float v) {
    float E = fexp2_(v * 1.4426950408889634f);
    return E * frcp_(1.f + E);
}
__device__ __forceinline__ float tanhf_(float v) {
    float E = fexp2_(v * 2.8853900817779268f);
    return (E - 1.f) * frcp_(E + 1.f);
}
__device__ __forceinline__ float4 sig4(float4 v) {
    return make_float4(sigf(v.x), sigf(v.y), sigf(v.z), sigf(v.w));
}
__device__ __forceinline__ float4 tanh4(float4 v) {
    return make_float4(tanhf_(v.x), tanhf_(v.y), tanhf_(v.z), tanhf_(v.w));
}

__device__ __forceinline__ void gbar(unsigned target) {
    __syncthreads();
    if (threadIdx.x == 0) {
        __threadfence();
        atomicAdd(&g_cnt, 1u);
        volatile unsigned* p = &g_cnt;
        while (*p < target) { __nanosleep(32); }
    }
    __syncthreads();
}

__device__ __forceinline__ void mma16816(float* acc, uint32_t a0, uint32_t a1,
                                         uint32_t a2, uint32_t a3,
                                         uint32_t b0, uint32_t b1) {
    asm volatile(
        "mma.sync.aligned.m16n8k16.row.col.f32.f16.f16.f32 "
        "{%0,%1,%2,%3},{%4,%5,%6,%7},{%8,%9},{%0,%1,%2,%3};"
        : "+f"(acc[0]), "+f"(acc[1]), "+f"(acc[2]), "+f"(acc[3])
        : "r"(a0), "r"(a1), "r"(a2), "r"(a3), "r"(b0), "r"(b1));
}

__global__ __launch_bounds__(NT, 3)
void lstm_persist(float* __restrict__ out, const float* __restrict__ Wih1) {
    __shared__ __align__(16) __half As[2][64 * SH];
    __shared__ __align__(16) __half Bs[2][64 * SH];

    const int NB = gridDim.x;
    const int t = threadIdx.x, bid = blockIdx.x;
    const int w = t >> 5, lane = t & 31;
    const int g4l = lane >> 2, ql = lane & 3;
    const int wm = w & 3, wn = w >> 2;
    const int wr0 = wm * 16, wn0 = wn * 32;
    const int srow = t >> 2, sseg = t & 3;      // staging: row 0..63, 16B seg 0..3

    // cell ownership: one float4 item per thread (needs NB*NT >= 65536)
    const int it = bid * NT + t;
    const bool own = it < 2 * BATCH * HID / 4;
    int layer = 0, cb = 0, ch4 = 0;
    if (own) { layer = it >> 15; int r4 = it & 32767; cb = r4 >> 7; ch4 = r4 & 127; }
    float4 cc = make_float4(0.f, 0.f, 0.f, 0.f);

    unsigned bt = 0;

    for (int k = 0; k <= TT; k++) {
        // ============ phase A: GEMM tiles ============
        for (int tt = bid; tt < NTILES; tt += NB) {
            int gm = tt >> 8, r = tt & 255;
            int sp = r & 1, q2 = r >> 1;
            int b0 = (q2 & 3) << 6, n0 = (q2 >> 2) << 6, kbeg = sp << 8;

            bool active, zeroA = false;
            const __half* Ap; const __half* Wp; float* outp;
            if (gm == 0) {
                active = (k < TT); zeroA = (k == 0);
                Ap = g_h1h[(k - 1) & 1]; Wp = g_wWhh1h; outp = g_p1[sp];
            } else if (gm == 1) {
                active = (k >= 1);
                Ap = g_h1h[(k - 1) & 1]; Wp = g_wWih2h; outp = g_p2[sp];
            } else {
                active = (k >= 1); zeroA = (k == 1);
                Ap = g_h2h[k & 1];       Wp = g_wWhh2h; outp = g_p2[2 + sp];
            }
            if (!active) continue;

            if (zeroA) {
                float4 z = make_float4(0.f, 0.f, 0.f, 0.f);
#pragma unroll
                for (int i = 0; i < 4; i++) {
                    int e = t + 256 * i;
                    int rr = e >> 4, c4 = e & 15;
                    ((float4*)outp)[(b0 + rr) * (G4 / 4) + (n0 >> 2) + c4] = z;
                }
                continue;
            }

            const __half* Asrc = Ap + (b0 + srow) * HID + kbeg + sseg * 8;
            const __half* Bsrc = Wp + (n0 + srow) * HID + kbeg + sseg * 8;
            const int sdst = srow * SH + sseg * 8;

            uint4 ra = __ldcg((const uint4*)Asrc);
            uint4 rb = __ldg((const uint4*)Bsrc);

            float acc[4][4];
#pragma unroll
            for (int a = 0; a < 4; a++)
#pragma unroll
                for (int b = 0; b < 4; b++) acc[a][b] = 0.f;

#pragma unroll 1
            for (int chn = 0; chn < 8; chn++) {
                int buf = chn & 1;
                *(uint4*)(&As[buf][sdst]) = ra;
                *(uint4*)(&Bs[buf][sdst]) = rb;
                __syncthreads();
                if (chn < 7) {
                    ra = __ldcg((const uint4*)(Asrc + (chn + 1) * 32));
                    rb = __ldg((const uint4*)(Bsrc + (chn + 1) * 32));
                }
                const __half* Ab = As[buf];
                const __half* Bb = Bs[buf];
#pragma unroll
                for (int kh = 0; kh < 2; kh++) {
                    int kb = kh * 16;
                    uint32_t a0 = *(const uint32_t*)(Ab + (wr0 + g4l) * SH + kb + 2 * ql);
                    uint32_t a1 = *(const uint32_t*)(Ab + (wr0 + 8 + g4l) * SH + kb + 2 * ql);
                    uint32_t a2 = *(const uint32_t*)(Ab + (wr0 + g4l) * SH + kb + 8 + 2 * ql);
                    uint32_t a3 = *(const uint32_t*)(Ab + (wr0 + 8 + g4l) * SH + kb + 8 + 2 * ql);
#pragma unroll
                    for (int ng = 0; ng < 4; ng++) {
                        const __half* bp = Bb + (wn0 + ng * 8 + g4l) * SH + kb + 2 * ql;
                        uint32_t b0r = *(const uint32_t*)bp;
                        uint32_t b1r = *(const uint32_t*)(bp + 8);
                        mma16816(acc[ng], a0, a1, a2, a3, b0r, b1r);
                    }
                }
            }

#pragma unroll
            for (int ng = 0; ng < 4; ng++) {
                int gc = n0 + wn0 + ng * 8 + 2 * ql;
                int m0 = b0 + wr0 + g4l;
                *(float2*)&outp[m0 * G4 + gc] = make_float2(acc[ng][0], acc[ng][1]);
                *(float2*)&outp[(m0 + 8) * G4 + gc] = make_float2(acc[ng][2], acc[ng][3]);
            }
        }

        bt += NB; gbar(bt);

        // ============ phase B: cell update ============
        if (own) {
            if (layer == 0) {
                if (k < TT) {
                    float xv = __ldg(&g_xt[k * BATCH + cb]);
                    float4 pre[4];
#pragma unroll
                    for (int g = 0; g < 4; g++) {
                        int idx = cb * 512 + g * 128 + ch4;
                        float4 pa = __ldcg(&((const float4*)g_p1[0])[idx]);
                        float4 pb = __ldcg(&((const float4*)g_p1[1])[idx]);
                        float4 bs = ((const float4*)g_bs1)[g * 128 + ch4];
                        float4 wv = ((const float4*)Wih1)[g * 128 + ch4];
                        pre[g] = make_float4(pa.x + pb.x + bs.x + xv * wv.x,
                                             pa.y + pb.y + bs.y + xv * wv.y,
                                             pa.z + pb.z + bs.z + xv * wv.z,
                                             pa.w + pb.w + bs.w + xv * wv.w);
                    }
                    float4 iv = sig4(pre[0]), fv = sig4(pre[1]);
                    float4 gv = tanh4(pre[2]), ov = sig4(pre[3]);
                    cc.x = fv.x * cc.x + iv.x * gv.x;
                    cc.y = fv.y * cc.y + iv.y * gv.y;
                    cc.z = fv.z * cc.z + iv.z * gv.z;
                    cc.w = fv.w * cc.w + iv.w * gv.w;
                    float4 tc = tanh4(cc);
                    __half2* H = (__half2*)g_h1h[k & 1];
                    H[cb * 256 + ch4 * 2]     = __floats2half2_rn(ov.x * tc.x, ov.y * tc.y);
                    H[cb * 256 + ch4 * 2 + 1] = __floats2half2_rn(ov.z * tc.z, ov.w * tc.w);
                }
            } else {
                if (k >= 1) {
                    int s = k - 1;
                    float4 pre[4];
#pragma unroll
                    for (int g = 0; g < 4; g++) {
                        int idx = cb * 512 + g * 128 + ch4;
                        float4 v = ((const float4*)g_bs2)[g * 128 + ch4];
#pragma unroll
                        for (int spp = 0; spp < 4; spp++) {
                            float4 p = __ldcg(&((const float4*)g_p2[spp])[idx]);
                            v.x += p.x; v.y += p.y; v.z += p.z; v.w += p.w;
                        }
                        pre[g] = v;
                    }
                    float4 iv = sig4(pre[0]), fv = sig4(pre[1]);
                    float4 gv = tanh4(pre[2]), ov = sig4(pre[3]);
                    cc.x = fv.x * cc.x + iv.x * gv.x;
                    cc.y = fv.y * cc.y + iv.y * gv.y;
                    cc.z = fv.z * cc.z + iv.z * gv.z;
                    cc.w = fv.w * cc.w + iv.w * gv.w;
                    float4 tc = tanh4(cc);
                    float4 hv = make_float4(ov.x * tc.x, ov.y * tc.y,
                                            ov.z * tc.z, ov.w * tc.w);
                    __half2* H = (__half2*)g_h2h[s & 1];
                    H[cb * 256 + ch4 * 2]     = __floats2half2_rn(hv.x, hv.y);
                    H[cb * 256 + ch4 * 2 + 1] = __floats2half2_rn(hv.z, hv.w);
                    if (s == TT - 1) ((float4*)out)[cb * 128 + ch4] = hv;
                }
            }
        }

        bt += NB; gbar(bt);
    }
}

extern "C" void kernel_launch(void* const* d_in, const int* in_sizes, int n_in,
                              void* d_out, int out_size) {
    (void)in_sizes; (void)n_in; (void)out_size;
    const float* x    = (const float*)d_in[0];
    const float* Wih1 = (const float*)d_in[1];
    const float* Whh1 = (const float*)d_in[2];
    const float* bih1 = (const float*)d_in[3];
    const float* bhh1 = (const float*)d_in[4];
    const float* Wih2 = (const float*)d_in[5];
    const float* Whh2 = (const float*)d_in[6];
    const float* bih2 = (const float*)d_in[7];
    const float* bhh2 = (const float*)d_in[8];
    float* out = (float*)d_out;

    static int nb = 0;
    if (nb == 0) {
        int dev = 0, sms = 0, occ = 0;
        cudaGetDevice(&dev);
        cudaDeviceGetAttribute(&sms, cudaDevAttrMultiProcessorCount, dev);
        cudaOccupancyMaxActiveBlocksPerMultiprocessor(&occ, lstm_persist, NT, 0);
        if (occ < 1) occ = 1;
        nb = sms * occ;
        if (nb > NTILES) nb = NTILES;
        if (nb < 256) nb = 256;       // cell ownership needs >= 65536 threads
    }

    init_kernel<<<1024, 256>>>(x, Whh1, Wih2, Whh2, bih1, bhh1, bih2, bhh2);
    lstm_persist<<<nb, NT>>>(out, Wih1);
}

// round 7
// speedup vs baseline: 4.1823x; 1.3861x over previous
#include <cuda_runtime.h>
#include <cuda_fp16.h>
#include <math.h>
#include <stdint.h>

#define BATCH 256
#define TT    1024
#define HID   512
#define NBL   384
#define NT    256
#define DSMEM 55296   /* 3 stages * (64+64) rows * 72 halves * 2B */

// ---------------- static device state ----------------
__device__ __half g_hc[2][BATCH * 1024];   // [buf][b][ h1(512) | h2(512) ]
__device__ __half g_w1p[2048 * 512];       // permuted Whh1, row p = hid*4+gate
__device__ __half g_w2p[2048 * 1024];      // permuted [Wih2 | Whh2] stacked in K
__device__ float  g_bs1p[2048];
__device__ float  g_bs2p[2048];
__device__ float  g_wih1p[2048];
__device__ float  g_xt[TT * BATCH];        // x transposed [k][b]
__device__ unsigned g_cnt;

__global__ void init_kernel(const float* __restrict__ x,
                            const float* __restrict__ Wih1,
                            const float* __restrict__ Whh1,
                            const float* __restrict__ bih1, const float* __restrict__ bhh1,
                            const float* __restrict__ Wih2,
                            const float* __restrict__ Whh2,
                            const float* __restrict__ bih2, const float* __restrict__ bhh2) {
    int i = blockIdx.x * blockDim.x + threadIdx.x;   // up to 2M
    if (i == 0) g_cnt = 0u;
    if (i < 2048) {
        int orig = (i & 3) * 512 + (i >> 2);         // gate*512 + hid
        g_bs1p[i]  = bih1[orig] + bhh1[orig];
        g_bs2p[i]  = bih2[orig] + bhh2[orig];
        g_wih1p[i] = Wih1[orig];
    }
    if (i < 2048 * 512) {
        int p = i >> 9, c = i & 511;
        int orig = (p & 3) * 512 + (p >> 2);
        g_w1p[i] = __float2half_rn(Whh1[orig * 512 + c]);
    }
    if (i < 2048 * 1024) {
        int p = i >> 10, c = i & 1023;
        int orig = (p & 3) * 512 + (p >> 2);
        float v = (c < 512) ? Wih2[orig * 512 + c] : Whh2[orig * 512 + (c - 512)];
        g_w2p[i] = __float2half_rn(v);
    }
    if (i < 2 * BATCH * 1024) {
        ((__half*)g_hc)[i] = __float2half_rn(0.f);
    }
    if (i < BATCH * TT) {
        int b = i >> 10, kk = i & 1023;
        g_xt[kk * BATCH + b] = x[i];
    }
}

// ---- MUFU-free activations ----
__device__ __forceinline__ float fexp2_(float y) {
    y = fminf(fmaxf(y, -30.f), 30.f);
    float r = y + 12582912.f;
    int   n = __float_as_int(r) - 0x4B400000;
    float f = y - (r - 12582912.f);
    float p = 1.5403530393381609e-4f;
    p = fmaf(p, f, 1.3333558146428443e-3f);
    p = fmaf(p, f, 9.6181291076284772e-3f);
    p = fmaf(p, f, 5.5504108664821580e-2f);
    p = fmaf(p, f, 2.4022650695910071e-1f);
    p = fmaf(p, f, 6.9314718055994531e-1f);
    p = fmaf(p, f, 1.0f);
    return p * __int_as_float((n + 127) << 23);
}
__device__ __forceinline__ float frcp_(float d) {
    float w = __int_as_float(0x7EF311C3 - __float_as_int(d));
    w = w * (2.f - d * w);
    w = w * (2.f - d * w);
    w = w * (2.f - d * w);
    return w;
}
__device__ __forceinline__ float sigf(float v) {
    float E = fexp2_(v * 1.4426950408889634f);
    return E * frcp_(1.f + E);
}
__device__ __forceinline__ float tanhf_(float v) {
    float E = fexp2_(v * 2.8853900817779268f);
    return (E - 1.f) * frcp_(E + 1.f);
}

// ---- async copy / ldmatrix / mma helpers ----
__device__ __forceinline__ void cp_cg(uint32_t dst, const void* src) {
    asm volatile("cp.async.cg.shared.global [%0], [%1], 16;" :: "r"(dst), "l"(src));
}
__device__ __forceinline__ void cp_ca(uint32_t dst, const void* src) {
    asm volatile("cp.async.ca.shared.global [%0], [%1], 16;" :: "r"(dst), "l"(src));
}
__device__ __forceinline__ void cp_commit() {
    asm volatile("cp.async.commit_group;");
}
template<int N> __device__ __forceinline__ void cp_wait() {
    asm volatile("cp.async.wait_group %0;" :: "n"(N));
}
__device__ __forceinline__ void ldsm4(uint32_t& r0, uint32_t& r1, uint32_t& r2,
                                      uint32_t& r3, uint32_t addr) {
    asm volatile("ldmatrix.sync.aligned.m8n8.x4.shared.b16 {%0,%1,%2,%3}, [%4];"
                 : "=r"(r0), "=r"(r1), "=r"(r2), "=r"(r3) : "r"(addr));
}
__device__ __forceinline__ void mma16816(float* acc, uint32_t a0, uint32_t a1,
                                         uint32_t a2, uint32_t a3,
                                         uint32_t b0, uint32_t b1) {
    asm volatile(
        "mma.sync.aligned.m16n8k16.row.col.f32.f16.f16.f32 "
        "{%0,%1,%2,%3},{%4,%5,%6,%7},{%8,%9},{%0,%1,%2,%3};"
        : "+f"(acc[0]), "+f"(acc[1]), "+f"(acc[2]), "+f"(acc[3])
        : "r"(a0), "r"(a1), "r"(a2), "r"(a3), "r"(b0), "r"(b1));
}

__device__ __forceinline__ void gbar(unsigned target) {
    __threadfence();
    __syncthreads();
    if (threadIdx.x == 0) {
        atomicAdd(&g_cnt, 1u);
        volatile unsigned* p = &g_cnt;
        while (*p < target) { __nanosleep(32); }
    }
    __syncthreads();
}

// ---- one stage of cp.async loads: A (ROWS x 64) + W (64 x 64), Kc=64 ----
template<int ROWS>
__device__ __forceinline__ void stage_load(uint32_t sb,
                                           const __half* __restrict__ Ag, int agst,
                                           const __half* __restrict__ Wg, int wgst,
                                           int ch) {
    const int t = threadIdx.x;
    constexpr int ASZ = ROWS * 72;
#pragma unroll
    for (int i = 0; i < ROWS * 8 / 256; i++) {
        int e = t + 256 * i, r = e >> 3, sg = e & 7;
        cp_cg(sb + (uint32_t)((r * 72 + sg * 8) * 2), Ag + r * agst + ch * 64 + sg * 8);
    }
#pragma unroll
    for (int i = 0; i < 2; i++) {
        int e = t + 256 * i, r = e >> 3, sg = e & 7;
        cp_ca(sb + (uint32_t)((ASZ + r * 72 + sg * 8) * 2), Wg + r * wgst + ch * 64 + sg * 8);
    }
}

// ---- full-K GEMM tile -> pre-activations in block smem (exch, stride 68 floats) ----
template<int ROWS, int NCH, int NG>
__device__ __forceinline__ void gemm_tile(const __half* __restrict__ Ag, int agst,
                                          const __half* __restrict__ Wg, int wgst,
                                          float* exch, uint32_t sbase) {
    constexpr int ASZ = ROWS * 72;
    constexpr int SSZ = ASZ + 64 * 72;       // halves per stage
    const int t = threadIdx.x, l = t & 31, w = t >> 5;
    constexpr int WMN = ROWS / 16;
    const int wm = w % WMN, wn = w / WMN;
    const int wn0 = wn * (NG * 8);

    const uint32_t aoff = (uint32_t)(((wm * 16 + (l & 15)) * 72 + (l >> 4) * 8) * 2);
    const uint32_t boff = (uint32_t)(((ASZ) + (wn0 + (l & 15)) * 72 + (l >> 4) * 8) * 2);

    float acc[NG][4];
#pragma unroll
    for (int a = 0; a < NG; a++)
#pragma unroll
        for (int b = 0; b < 4; b++) acc[a][b] = 0.f;

    stage_load<ROWS>(sbase, Ag, agst, Wg, wgst, 0); cp_commit();
    stage_load<ROWS>(sbase + SSZ * 2, Ag, agst, Wg, wgst, 1); cp_commit();

#pragma unroll 1
    for (int ch = 0; ch < NCH; ch++) {
        cp_wait<1>();
        __syncthreads();
        if (ch + 2 < NCH)
            stage_load<ROWS>(sbase + (uint32_t)(((ch + 2) % 3) * SSZ * 2),
                             Ag, agst, Wg, wgst, ch + 2);
        cp_commit();   // always commit (empty groups keep wait_group aligned)

        uint32_t sb = sbase + (uint32_t)((ch % 3) * SSZ * 2);
#pragma unroll
        for (int ks = 0; ks < 4; ks++) {
            uint32_t a0, a1, a2, a3;
            ldsm4(a0, a1, a2, a3, sb + aoff + ks * 32);
            uint32_t b0, b1, b2, b3;
            ldsm4(b0, b1, b2, b3, sb + boff + ks * 32);
            mma16816(acc[0], a0, a1, a2, a3, b0, b2);
            mma16816(acc[1], a0, a1, a2, a3, b1, b3);
            if (NG == 4) {
                uint32_t c0, c1, c2, c3;
                ldsm4(c0, c1, c2, c3, sb + boff + 16 * 72 * 2 + ks * 32);
                mma16816(acc[2], a0, a1, a2, a3, c0, c2);
                mma16816(acc[3], a0, a1, a2, a3, c1, c3);
            }
        }
    }
    __syncthreads();   // done reading stages; exch aliases stage memory

#pragma unroll
    for (int ng = 0; ng < NG; ng++) {
        int m = wm * 16 + (l >> 2);
        int c = wn0 + ng * 8 + 2 * (l & 3);
        *(float2*)(exch + m * 68 + c)       = make_float2(acc[ng][0], acc[ng][1]);
        *(float2*)(exch + (m + 8) * 68 + c) = make_float2(acc[ng][2], acc[ng][3]);
    }
}

// ---------------- persistent kernel: one barrier per iteration ----------------
__global__ __launch_bounds__(NT, 3)
void lstm_persist(float* __restrict__ out) {
    extern __shared__ __align__(16) char dsm[];
    __shared__ float sc[1024];               // block-local cell state
    float* exch = (float*)dsm;
    uint32_t sbase = (uint32_t)__cvta_generic_to_shared(dsm);

    const int bid = blockIdx.x, t = threadIdx.x;
    const bool isL1 = bid < 128;
    int b0, n0;
    if (isL1) { b0 = (bid & 3) * 64; n0 = (bid >> 2) * 64; }
    else      { int id = bid - 128; b0 = (id & 7) * 32; n0 = (id >> 3) * 64; }

    for (int i = t; i < 1024; i += NT) sc[i] = 0.f;   // own items, no sync needed

    unsigned bt = 0;

    for (int k = 0; k <= TT; k++) {
        const __half* hcr = g_hc[(k - 1) & 1] + b0 * 1024;
        __half* hcw = g_hc[k & 1];

        if (isL1) {
            if (k < TT) {
                gemm_tile<64, 8, 4>(hcr, 1024, g_w1p + n0 * 512, 512, exch, sbase);
                __syncthreads();
#pragma unroll
                for (int j = 0; j < 4; j++) {
                    int item = t + 256 * j, bl = item >> 4, hl = item & 15;
                    float4 v  = *(float4*)(exch + bl * 68 + hl * 4);
                    float4 bs = *(const float4*)(g_bs1p + n0 + hl * 4);
                    float4 wv = *(const float4*)(g_wih1p + n0 + hl * 4);
                    float xv = g_xt[k * BATCH + b0 + bl];
                    float i_ = sigf  (v.x + bs.x + xv * wv.x);
                    float f_ = sigf  (v.y + bs.y + xv * wv.y);
                    float g_ = tanhf_(v.z + bs.z + xv * wv.z);
                    float o_ = sigf  (v.w + bs.w + xv * wv.w);
                    float c = fmaf(f_, sc[item], i_ * g_);
                    sc[item] = c;
                    hcw[(b0 + bl) * 1024 + (n0 >> 2) + hl] = __float2half_rn(o_ * tanhf_(c));
                }
            }
        } else {
            if (k >= 1) {
                gemm_tile<32, 16, 2>(hcr, 1024, g_w2p + n0 * 1024, 1024, exch, sbase);
                __syncthreads();
#pragma unroll
                for (int j = 0; j < 2; j++) {
                    int item = t + 256 * j, bl = item >> 4, hl = item & 15;
                    float4 v  = *(float4*)(exch + bl * 68 + hl * 4);
                    float4 bs = *(const float4*)(g_bs2p + n0 + hl * 4);
                    float i_ = sigf  (v.x + bs.x);
                    float f_ = sigf  (v.y + bs.y);
                    float g_ = tanhf_(v.z + bs.z);
                    float o_ = sigf  (v.w + bs.w);
                    float c = fmaf(f_, sc[item], i_ * g_);
                    sc[item] = c;
                    float hv = o_ * tanhf_(c);
                    int hid = (n0 >> 2) + hl;
                    hcw[(b0 + bl) * 1024 + 512 + hid] = __float2half_rn(hv);
                    if (k == TT) out[(b0 + bl) * 512 + hid] = hv;
                }
            }
        }

        bt += NBL;
        gbar(bt);
    }
}

extern "C" void kernel_launch(void* const* d_in, const int* in_sizes, int n_in,
                              void* d_out, int out_size) {
    (void)in_sizes; (void)n_in; (void)out_size;
    const float* x    = (const float*)d_in[0];
    const float* Wih1 = (const float*)d_in[1];
    const float* Whh1 = (const float*)d_in[2];
    const float* bih1 = (const float*)d_in[3];
    const float* bhh1 = (const float*)d_in[4];
    const float* Wih2 = (const float*)d_in[5];
    const float* Whh2 = (const float*)d_in[6];
    const float* bih2 = (const float*)d_in[7];
    const float* bhh2 = (const float*)d_in[8];
    float* out = (float*)d_out;

    cudaFuncSetAttribute(lstm_persist, cudaFuncAttributeMaxDynamicSharedMemorySize, DSMEM);

    init_kernel<<<4096, 512>>>(x, Wih1, Whh1, bih1, bhh1, Wih2, Whh2, bih2, bhh2);
    lstm_persist<<<NBL, NT, DSMEM>>>(out);
}

// round 8
// speedup vs baseline: 4.3583x; 1.0421x over previous
#include <cuda_runtime.h>
#include <cuda_fp16.h>
#include <math.h>
#include <stdint.h>

#define BATCH 256
#define TT    1024
#define NBL   96
#define NT    512

// smem layout (bytes)
#define SSB   18432            /* one A stage: 128 rows x 72 halves x 2B */
#define WOFF  67584            /* stages/exch region size = max(3*SSB, L1 exch 128*132*4) */
#define COFF  200704           /* WOFF + 133120 (max W tile) */
#define DSMEM 217088           /* COFF + 16384 (max c) */

// ---------------- static device state ----------------
__device__ __half g_hc[2][BATCH * 1024];   // [buf][b][ h1(512) | h2(512) ]
__device__ __half g_w1p[2048 * 512];       // permuted Whh1, row p = hid*4+gate
__device__ __half g_w2p[2048 * 1024];      // permuted [Wih2 | Whh2] stacked in K
__device__ float  g_bs1p[2048];
__device__ float  g_bs2p[2048];
__device__ float  g_wih1p[2048];
__device__ float  g_xt[TT * BATCH];
__device__ unsigned g_cnt;

__global__ void init_kernel(const float* __restrict__ x,
                            const float* __restrict__ Wih1,
                            const float* __restrict__ Whh1,
                            const float* __restrict__ bih1, const float* __restrict__ bhh1,
                            const float* __restrict__ Wih2,
                            const float* __restrict__ Whh2,
                            const float* __restrict__ bih2, const float* __restrict__ bhh2) {
    int i = blockIdx.x * blockDim.x + threadIdx.x;
    if (i == 0) g_cnt = 0u;
    if (i < 2048) {
        int orig = (i & 3) * 512 + (i >> 2);
        g_bs1p[i]  = bih1[orig] + bhh1[orig];
        g_bs2p[i]  = bih2[orig] + bhh2[orig];
        g_wih1p[i] = Wih1[orig];
    }
    if (i < 2048 * 512) {
        int p = i >> 9, c = i & 511;
        int orig = (p & 3) * 512 + (p >> 2);
        g_w1p[i] = __float2half_rn(Whh1[orig * 512 + c]);
    }
    if (i < 2048 * 1024) {
        int p = i >> 10, c = i & 1023;
        int orig = (p & 3) * 512 + (p >> 2);
        float v = (c < 512) ? Wih2[orig * 512 + c] : Whh2[orig * 512 + (c - 512)];
        g_w2p[i] = __float2half_rn(v);
    }
    if (i < 2 * BATCH * 1024) ((__half*)g_hc)[i] = __float2half_rn(0.f);
    if (i < BATCH * TT) {
        int b = i >> 10, kk = i & 1023;
        g_xt[kk * BATCH + b] = x[i];
    }
}

// ---- MUFU-free activations ----
__device__ __forceinline__ float fexp2_(float y) {
    y = fminf(fmaxf(y, -30.f), 30.f);
    float r = y + 12582912.f;
    int   n = __float_as_int(r) - 0x4B400000;
    float f = y - (r - 12582912.f);
    float p = 1.5403530393381609e-4f;
    p = fmaf(p, f, 1.3333558146428443e-3f);
    p = fmaf(p, f, 9.6181291076284772e-3f);
    p = fmaf(p, f, 5.5504108664821580e-2f);
    p = fmaf(p, f, 2.4022650695910071e-1f);
    p = fmaf(p, f, 6.9314718055994531e-1f);
    p = fmaf(p, f, 1.0f);
    return p * __int_as_float((n + 127) << 23);
}
__device__ __forceinline__ float frcp_(float d) {
    float w = __int_as_float(0x7EF311C3 - __float_as_int(d));
    w = w * (2.f - d * w);
    w = w * (2.f - d * w);
    w = w * (2.f - d * w);
    return w;
}
__device__ __forceinline__ float sigf(float v) {
    float E = fexp2_(v * 1.4426950408889634f);
    return E * frcp_(1.f + E);
}
__device__ __forceinline__ float tanhf_(float v) {
    float E = fexp2_(v * 2.8853900817779268f);
    return (E - 1.f) * frcp_(E + 1.f);
}

// ---- async copy / ldmatrix / mma ----
__device__ __forceinline__ void cp_cg(uint32_t dst, const void* src) {
    asm volatile("cp.async.cg.shared.global [%0], [%1], 16;" :: "r"(dst), "l"(src));
}
__device__ __forceinline__ void cp_commit() { asm volatile("cp.async.commit_group;"); }
template<int N> __device__ __forceinline__ void cp_wait() {
    asm volatile("cp.async.wait_group %0;" :: "n"(N));
}
__device__ __forceinline__ void ldsm4(uint32_t& r0, uint32_t& r1, uint32_t& r2,
                                      uint32_t& r3, uint32_t addr) {
    asm volatile("ldmatrix.sync.aligned.m8n8.x4.shared.b16 {%0,%1,%2,%3}, [%4];"
                 : "=r"(r0), "=r"(r1), "=r"(r2), "=r"(r3) : "r"(addr));
}
__device__ __forceinline__ void mma16816(float* acc, uint32_t a0, uint32_t a1,
                                         uint32_t a2, uint32_t a3,
                                         uint32_t b0, uint32_t b1) {
    asm volatile(
        "mma.sync.aligned.m16n8k16.row.col.f32.f16.f16.f32 "
        "{%0,%1,%2,%3},{%4,%5,%6,%7},{%8,%9},{%0,%1,%2,%3};"
        : "+f"(acc[0]), "+f"(acc[1]), "+f"(acc[2]), "+f"(acc[3])
        : "r"(a0), "r"(a1), "r"(a2), "r"(a3), "r"(b0), "r"(b1));
}

__device__ __forceinline__ void gbar(unsigned target) {
    __threadfence();
    __syncthreads();
    if (threadIdx.x == 0) {
        atomicAdd(&g_cnt, 1u);
        volatile unsigned* p = &g_cnt;
        while (*p < target) { __nanosleep(32); }
    }
    __syncthreads();
}

// ---------------- templated block body ----------------
// GROWS gate rows, KTOT K depth, LAYER 0/1. Batch tile fixed 128 rows.
template<int GROWS, int KTOT, int LAYER>
__device__ __forceinline__ void run_block(char* dsm, int b0, int n0,
                                          float* __restrict__ out) {
    constexpr int NCH = KTOT / 64;
    constexpr int WST = KTOT + 8;          // W smem stride (halves)
    constexpr int NGF = GROWS / 32;        // n-frags per warp (4 or 2)
    constexpr int EST = GROWS + 4;         // exch stride (floats)
    constexpr int HL  = GROWS / 4;         // hidden units per block

    float* exch = (float*)dsm;
    float* sc   = (float*)(dsm + COFF);
    const uint32_t sb0 = (uint32_t)__cvta_generic_to_shared(dsm);
    const uint32_t wb  = sb0 + WOFF;

    const int t = threadIdx.x;
    const int w = t >> 5, l = t & 31;
    const int wm = w & 3, wn = w >> 2;
    const int m0 = wm * 32;
    const int n0w = wn * (NGF * 8);
    const int arow = l & 15, acol8 = (l >> 4) * 8;

    // ---- one-time: preload weight tile into persistent smem ----
    {
        const __half* Wg = (LAYER == 0) ? (g_w1p + n0 * KTOT) : (g_w2p + n0 * KTOT);
        constexpr int SEGS = KTOT / 8;
#pragma unroll
        for (int i = 0; i < 16; i++) {
            int e = t + 512 * i;
            int r = e / SEGS, sg = e % SEGS;
            cp_cg(wb + (uint32_t)((r * WST + sg * 8) * 2), Wg + r * KTOT + sg * 8);
        }
        cp_commit(); cp_wait<0>();
        for (int i = t; i < 128 * HL; i += NT) sc[i] = 0.f;
        __syncthreads();
    }

    unsigned bt = 0;

    for (int k = 0; k <= TT; k++) {
        const bool active = (LAYER == 0) ? (k < TT) : (k >= 1);
        if (active) {
            const __half* Ag = g_hc[(k - 1) & 1] + b0 * 1024;

            // stage loader: A chunk (128 x 64 halves) into stage s
#define STAGE_LOAD(s, ch)                                                        \
            {                                                                    \
                _Pragma("unroll")                                                \
                for (int i_ = 0; i_ < 2; i_++) {                                 \
                    int e_ = t + 512 * i_, r_ = e_ >> 3, sg_ = e_ & 7;           \
                    cp_cg(sb0 + (uint32_t)((s) * SSB + (r_ * 72 + sg_ * 8) * 2), \
                          Ag + r_ * 1024 + (ch) * 64 + sg_ * 8);                 \
                }                                                                \
            }

            float acc[2][NGF][4];
#pragma unroll
            for (int a = 0; a < 2; a++)
#pragma unroll
                for (int b = 0; b < NGF; b++)
#pragma unroll
                    for (int c = 0; c < 4; c++) acc[a][b][c] = 0.f;

            STAGE_LOAD(0, 0); cp_commit();
            STAGE_LOAD(1, 1); cp_commit();

#pragma unroll 1
            for (int ch = 0; ch < NCH; ch++) {
                cp_wait<1>();
                __syncthreads();
                if (ch + 2 < NCH) STAGE_LOAD((ch + 2) % 3, ch + 2);
                cp_commit();

                const uint32_t stg = sb0 + (uint32_t)((ch % 3) * SSB);
#pragma unroll
                for (int ks = 0; ks < 4; ks++) {
                    uint32_t a0, a1, a2, a3, a4, a5, a6, a7;
                    ldsm4(a0, a1, a2, a3,
                          stg + (uint32_t)(((m0 + arow) * 72 + ks * 16 + acol8) * 2));
                    ldsm4(a4, a5, a6, a7,
                          stg + (uint32_t)(((m0 + 16 + arow) * 72 + ks * 16 + acol8) * 2));
                    const int kcol = ch * 64 + ks * 16 + acol8;
#pragma unroll
                    for (int bg = 0; bg < NGF / 2; bg++) {
                        uint32_t b0r, b1r, b2r, b3r;
                        ldsm4(b0r, b1r, b2r, b3r,
                              wb + (uint32_t)(((n0w + bg * 16 + arow) * WST + kcol) * 2));
                        mma16816(acc[0][bg * 2 + 0], a0, a1, a2, a3, b0r, b2r);
                        mma16816(acc[0][bg * 2 + 1], a0, a1, a2, a3, b1r, b3r);
                        mma16816(acc[1][bg * 2 + 0], a4, a5, a6, a7, b0r, b2r);
                        mma16816(acc[1][bg * 2 + 1], a4, a5, a6, a7, b1r, b3r);
                    }
                }
            }
#undef STAGE_LOAD

            cp_wait<0>();
            __syncthreads();           // stages free; exch aliases them

            // epilogue -> exch (pre-activations)
#pragma unroll
            for (int mf = 0; mf < 2; mf++)
#pragma unroll
                for (int ng = 0; ng < NGF; ng++) {
                    int row = m0 + mf * 16 + (l >> 2);
                    int col = n0w + ng * 8 + 2 * (l & 3);
                    *(float2*)(exch + row * EST + col) =
                        make_float2(acc[mf][ng][0], acc[mf][ng][1]);
                    *(float2*)(exch + (row + 8) * EST + col) =
                        make_float2(acc[mf][ng][2], acc[mf][ng][3]);
                }
            __syncthreads();

            // ---- cell update ----
            __half* hcw = g_hc[k & 1];
            const int hbase = (LAYER == 0) ? (n0 >> 2) : (512 + (n0 >> 2));
#pragma unroll
            for (int j = 0; j < HL / 4; j++) {
                int item = t + NT * j;
                int bl = item / HL, hl = item % HL;
                float4 v = *(float4*)(exch + bl * EST + hl * 4);
                float4 bs = *(const float4*)(((LAYER == 0) ? g_bs1p : g_bs2p) + n0 + hl * 4);
                float pi = v.x + bs.x, pf = v.y + bs.y, pg = v.z + bs.z, po = v.w + bs.w;
                if (LAYER == 0) {
                    float xv = g_xt[k * BATCH + b0 + bl];
                    float4 wv = *(const float4*)(g_wih1p + n0 + hl * 4);
                    pi += xv * wv.x; pf += xv * wv.y; pg += xv * wv.z; po += xv * wv.w;
                }
                float i_ = sigf(pi), f_ = sigf(pf), g_ = tanhf_(pg), o_ = sigf(po);
                float c = fmaf(f_, sc[item], i_ * g_);
                sc[item] = c;
                float hv = o_ * tanhf_(c);
                hcw[(b0 + bl) * 1024 + hbase + hl] = __float2half_rn(hv);
                if (LAYER == 1 && k == TT)
                    out[(b0 + bl) * 512 + (n0 >> 2) + hl] = hv;
            }
        }

        bt += NBL;
        gbar(bt);
    }
}

__global__ __launch_bounds__(NT, 1)
void lstm_persist(float* __restrict__ out) {
    extern __shared__ __align__(16) char dsm[];
    const int bid = blockIdx.x;
    if (bid < 32) {
        int b0 = (bid & 1) * 128, n0 = (bid >> 1) * 128;
        run_block<128, 512, 0>(dsm, b0, n0, out);
    } else {
        int id = bid - 32;
        int b0 = (id & 1) * 128, n0 = (id >> 1) * 64;
        run_block<64, 1024, 1>(dsm, b0, n0, out);
    }
}

extern "C" void kernel_launch(void* const* d_in, const int* in_sizes, int n_in,
                              void* d_out, int out_size) {
    (void)in_sizes; (void)n_in; (void)out_size;
    const float* x    = (const float*)d_in[0];
    const float* Wih1 = (const float*)d_in[1];
    const float* Whh1 = (const float*)d_in[2];
    const float* bih1 = (const float*)d_in[3];
    const float* bhh1 = (const float*)d_in[4];
    const float* Wih2 = (const float*)d_in[5];
    const float* Whh2 = (const float*)d_in[6];
    const float* bih2 = (const float*)d_in[7];
    const float* bhh2 = (const float*)d_in[8];
    float* out = (float*)d_out;

    cudaFuncSetAttribute(lstm_persist, cudaFuncAttributeMaxDynamicSharedMemorySize, DSMEM);

    init_kernel<<<4096, 512>>>(x, Wih1, Whh1, bih1, bhh1, Wih2, Whh2, bih2, bhh2);
    lstm_persist<<<NBL, NT, DSMEM>>>(out);
}

// round 10
// speedup vs baseline: 4.5109x; 1.0350x over previous
#include <cuda_runtime.h>
#include <cuda_fp16.h>
#include <math.h>
#include <stdint.h>

#define BATCH 256
#define TT    1024
#define NBL   96
#define NT    512

// smem layout (bytes)
#define SSB   18432            /* one A stage: 128 rows x 72 halves x 2B */
#define WOFF  67584            /* stages/exch region size */
#define COFF  200704           /* WOFF + 133120 (max W tile) */
#define DSMEM 217088           /* COFF + 16384 (max c) */

// ---------------- static device state ----------------
__device__ __half g_hc[2][BATCH * 1024];   // [buf][b][ h1(512) | h2(512) ]
__device__ __half g_w1p[2048 * 512];       // permuted Whh1, row p = hid*4+gate
__device__ __half g_w2p[2048 * 1024];      // permuted [Wih2 | Whh2] stacked in K
__device__ float  g_bs1p[2048];
__device__ float  g_bs2p[2048];
__device__ float  g_wih1p[2048];
__device__ float  g_xt[TT * BATCH];
__device__ unsigned g_cnt;

__global__ void init_kernel(const float* __restrict__ x,
                            const float* __restrict__ Wih1,
                            const float* __restrict__ Whh1,
                            const float* __restrict__ bih1, const float* __restrict__ bhh1,
                            const float* __restrict__ Wih2,
                            const float* __restrict__ Whh2,
                            const float* __restrict__ bih2, const float* __restrict__ bhh2) {
    int i = blockIdx.x * blockDim.x + threadIdx.x;
    if (i == 0) g_cnt = 0u;
    if (i < 2048) {
        int orig = (i & 3) * 512 + (i >> 2);
        g_bs1p[i]  = bih1[orig] + bhh1[orig];
        g_bs2p[i]  = bih2[orig] + bhh2[orig];
        g_wih1p[i] = Wih1[orig];
    }
    if (i < 2048 * 512) {
        int p = i >> 9, c = i & 511;
        int orig = (p & 3) * 512 + (p >> 2);
        g_w1p[i] = __float2half_rn(Whh1[orig * 512 + c]);
    }
    if (i < 2048 * 1024) {
        int p = i >> 10, c = i & 1023;
        int orig = (p & 3) * 512 + (p >> 2);
        float v = (c < 512) ? Wih2[orig * 512 + c] : Whh2[orig * 512 + (c - 512)];
        g_w2p[i] = __float2half_rn(v);
    }
    if (i < 2 * BATCH * 1024) ((__half*)g_hc)[i] = __float2half_rn(0.f);
    if (i < BATCH * TT) {
        int b = i >> 10, kk = i & 1023;
        g_xt[kk * BATCH + b] = x[i];
    }
}

// ---- MUFU activations: ex2.approx + rcp.approx (1-2 ulp) ----
__device__ __forceinline__ float ex2f(float v) {
    float r;
    asm("ex2.approx.ftz.f32 %0, %1;" : "=f"(r) : "f"(v));
    return r;
}
__device__ __forceinline__ float rcpf(float v) {
    float r;
    asm("rcp.approx.ftz.f32 %0, %1;" : "=f"(r) : "f"(v));
    return r;
}
__device__ __forceinline__ float sigf(float v) {
    // 1/(1+e^-v)
    return rcpf(1.f + ex2f(v * -1.4426950408889634f));
}
__device__ __forceinline__ float tanhf_(float v) {
    // 1 - 2/(e^{2v}+1)
    return fmaf(-2.f, rcpf(ex2f(v * 2.8853900817779268f) + 1.f), 1.f);
}

// ---- async copy / ldmatrix / mma ----
__device__ __forceinline__ void cp_cg(uint32_t dst, const void* src) {
    asm volatile("cp.async.cg.shared.global [%0], [%1], 16;" :: "r"(dst), "l"(src));
}
__device__ __forceinline__ void cp_commit() { asm volatile("cp.async.commit_group;"); }
template<int N> __device__ __forceinline__ void cp_wait() {
    asm volatile("cp.async.wait_group %0;" :: "n"(N));
}
__device__ __forceinline__ void ldsm4(uint32_t& r0, uint32_t& r1, uint32_t& r2,
                                      uint32_t& r3, uint32_t addr) {
    asm volatile("ldmatrix.sync.aligned.m8n8.x4.shared.b16 {%0,%1,%2,%3}, [%4];"
                 : "=r"(r0), "=r"(r1), "=r"(r2), "=r"(r3) : "r"(addr));
}
__device__ __forceinline__ void mma16816(float* acc, uint32_t a0, uint32_t a1,
                                         uint32_t a2, uint32_t a3,
                                         uint32_t b0, uint32_t b1) {
    asm volatile(
        "mma.sync.aligned.m16n8k16.row.col.f32.f16.f16.f32 "
        "{%0,%1,%2,%3},{%4,%5,%6,%7},{%8,%9},{%0,%1,%2,%3};"
        : "+f"(acc[0]), "+f"(acc[1]), "+f"(acc[2]), "+f"(acc[3])
        : "r"(a0), "r"(a1), "r"(a2), "r"(a3), "r"(b0), "r"(b1));
}

__device__ __forceinline__ void gbar(unsigned target) {
    __threadfence();
    __syncthreads();
    if (threadIdx.x == 0) {
        atomicAdd(&g_cnt, 1u);
        volatile unsigned* p = &g_cnt;
        while (*p < target) { __nanosleep(32); }
    }
    __syncthreads();
}

// ---------------- templated block body ----------------
// GROWS gate rows, KTOT K depth, LAYER 0/1. Batch tile fixed 128 rows.
template<int GROWS, int KTOT, int LAYER>
__device__ __forceinline__ void run_block(char* dsm, int b0, int n0,
                                          float* __restrict__ out) {
    constexpr int NCH = KTOT / 64;
    constexpr int WST = KTOT + 8;          // W smem stride (halves)
    constexpr int NGF = GROWS / 32;        // n-frags per warp (4 or 2)
    constexpr int EST = GROWS + 4;         // exch stride (floats)
    constexpr int HL  = GROWS / 4;         // hidden units per block

    float* exch = (float*)dsm;
    float* sc   = (float*)(dsm + COFF);
    const uint32_t sb0 = (uint32_t)__cvta_generic_to_shared(dsm);
    const uint32_t wb  = sb0 + WOFF;

    const int t = threadIdx.x;
    const int w = t >> 5, l = t & 31;
    const int wm = w & 3, wn = w >> 2;
    const int m0 = wm * 32;
    const int n0w = wn * (NGF * 8);
    const int arow = l & 15, acol8 = (l >> 4) * 8;

    // ---- one-time: preload weight tile into persistent smem ----
    {
        const __half* Wg = (LAYER == 0) ? (g_w1p + n0 * KTOT) : (g_w2p + n0 * KTOT);
        constexpr int SEGS = KTOT / 8;
#pragma unroll
        for (int i = 0; i < 16; i++) {
            int e = t + 512 * i;
            int r = e / SEGS, sg = e % SEGS;
            cp_cg(wb + (uint32_t)((r * WST + sg * 8) * 2), Wg + r * KTOT + sg * 8);
        }
        cp_commit(); cp_wait<0>();
        for (int i = t; i < 128 * HL; i += NT) sc[i] = 0.f;
        __syncthreads();
    }

    unsigned bt = 0;

    for (int k = 0; k <= TT; k++) {
        const bool active = (LAYER == 0) ? (k < TT) : (k >= 1);
        if (active) {
            const __half* Ag = g_hc[(k - 1) & 1] + b0 * 1024;

#define STAGE_LOAD(s, ch)                                                        \
            {                                                                    \
                _Pragma("unroll")                                                \
                for (int i_ = 0; i_ < 2; i_++) {                                 \
                    int e_ = t + 512 * i_, r_ = e_ >> 3, sg_ = e_ & 7;           \
                    cp_cg(sb0 + (uint32_t)((s) * SSB + (r_ * 72 + sg_ * 8) * 2), \
                          Ag + r_ * 1024 + (ch) * 64 + sg_ * 8);                 \
                }                                                                \
            }

            float acc[2][NGF][4];
#pragma unroll
            for (int a = 0; a < 2; a++)
#pragma unroll
                for (int b = 0; b < NGF; b++)
#pragma unroll
                    for (int c = 0; c < 4; c++) acc[a][b][c] = 0.f;

            STAGE_LOAD(0, 0); cp_commit();
            STAGE_LOAD(1, 1); cp_commit();

#pragma unroll 1
            for (int ch = 0; ch < NCH; ch++) {
                cp_wait<1>();
                __syncthreads();
                if (ch + 2 < NCH) STAGE_LOAD((ch + 2) % 3, ch + 2);
                cp_commit();

                const uint32_t stg = sb0 + (uint32_t)((ch % 3) * SSB);
#pragma unroll
                for (int ks = 0; ks < 4; ks++) {
                    uint32_t a0, a1, a2, a3, a4, a5, a6, a7;
                    ldsm4(a0, a1, a2, a3,
                          stg + (uint32_t)(((m0 + arow) * 72 + ks * 16 + acol8) * 2));
                    ldsm4(a4, a5, a6, a7,
                          stg + (uint32_t)(((m0 + 16 + arow) * 72 + ks * 16 + acol8) * 2));
                    const int kcol = ch * 64 + ks * 16 + acol8;
#pragma unroll
                    for (int bg = 0; bg < NGF / 2; bg++) {
                        uint32_t b0r, b1r, b2r, b3r;
                        ldsm4(b0r, b1r, b2r, b3r,
                              wb + (uint32_t)(((n0w + bg * 16 + arow) * WST + kcol) * 2));
                        mma16816(acc[0][bg * 2 + 0], a0, a1, a2, a3, b0r, b2r);
                        mma16816(acc[0][bg * 2 + 1], a0, a1, a2, a3, b1r, b3r);
                        mma16816(acc[1][bg * 2 + 0], a4, a5, a6, a7, b0r, b2r);
                        mma16816(acc[1][bg * 2 + 1], a4, a5, a6, a7, b1r, b3r);
                    }
                }
            }
#undef STAGE_LOAD

            cp_wait<0>();
            __syncthreads();           // stages free; exch aliases them

            // epilogue -> exch (pre-activations)
#pragma unroll
            for (int mf = 0; mf < 2; mf++)
#pragma unroll
                for (int ng = 0; ng < NGF; ng++) {
                    int row = m0 + mf * 16 + (l >> 2);
                    int col = n0w + ng * 8 + 2 * (l & 3);
                    *(float2*)(exch + row * EST + col) =
                        make_float2(acc[mf][ng][0], acc[mf][ng][1]);
                    *(float2*)(exch + (row + 8) * EST + col) =
                        make_float2(acc[mf][ng][2], acc[mf][ng][3]);
                }
            __syncthreads();

            // ---- cell update ----
            __half* hcw = g_hc[k & 1];
            const int hbase = (LAYER == 0) ? (n0 >> 2) : (512 + (n0 >> 2));
#pragma unroll
            for (int j = 0; j < HL / 4; j++) {
                int item = t + NT * j;
                int bl = item / HL, hl = item % HL;
                float4 v = *(float4*)(exch + bl * EST + hl * 4);
                float4 bs = *(const float4*)(((LAYER == 0) ? g_bs1p : g_bs2p) + n0 + hl * 4);
                float pi = v.x + bs.x, pf = v.y + bs.y, pg = v.z + bs.z, po = v.w + bs.w;
                if (LAYER == 0) {
                    float xv = g_xt[k * BATCH + b0 + bl];
                    float4 wv = *(const float4*)(g_wih1p + n0 + hl * 4);
                    pi += xv * wv.x; pf += xv * wv.y; pg += xv * wv.z; po += xv * wv.w;
                }
                float i_ = sigf(pi), f_ = sigf(pf), g_ = tanhf_(pg), o_ = sigf(po);
                float c = fmaf(f_, sc[item], i_ * g_);
                sc[item] = c;
                float hv = o_ * tanhf_(c);
                hcw[(b0 + bl) * 1024 + hbase + hl] = __float2half_rn(hv);
                if (LAYER == 1 && k == TT)
                    out[(b0 + bl) * 512 + (n0 >> 2) + hl] = hv;
            }
        }

        bt += NBL;
        gbar(bt);
    }
}

__global__ __launch_bounds__(NT, 1)
void lstm_persist(float* __restrict__ out) {
    extern __shared__ __align__(16) char dsm[];
    const int bid = blockIdx.x;
    if (bid < 32) {
        int b0 = (bid & 1) * 128, n0 = (bid >> 1) * 128;
        run_block<128, 512, 0>(dsm, b0, n0, out);
    } else {
        int id = bid - 32;
        int b0 = (id & 1) * 128, n0 = (id >> 1) * 64;
        run_block<64, 1024, 1>(dsm, b0, n0, out);
    }
}

extern "C" void kernel_launch(void* const* d_in, const int* in_sizes, int n_in,
                              void* d_out, int out_size) {
    (void)in_sizes; (void)n_in; (void)out_size;
    const float* x    = (const float*)d_in[0];
    const float* Wih1 = (const float*)d_in[1];
    const float* Whh1 = (const float*)d_in[2];
    const float* bih1 = (const float*)d_in[3];
    const float* bhh1 = (const float*)d_in[4];
    const float* Wih2 = (const float*)d_in[5];
    const float* Whh2 = (const float*)d_in[6];
    const float* bih2 = (const float*)d_in[7];
    const float* bhh2 = (const float*)d_in[8];
    float* out = (float*)d_out;

    cudaFuncSetAttribute(lstm_persist, cudaFuncAttributeMaxDynamicSharedMemorySize, DSMEM);

    init_kernel<<<4096, 512>>>(x, Wih1, Whh1, bih1, bhh1, Wih2, Whh2, bih2, bhh2);
    lstm_persist<<<NBL, NT, DSMEM>>>(out);
}